// round 12
// baseline (speedup 1.0000x reference)
#include <cuda_runtime.h>
#include <cuda_fp16.h>

#define N_NODES 100000
#define FEAT    128
#define CLS     64
#define CAP     96     // max in-degree slots per node (P(overflow) ~ 1e-20 at mean 16)

// Scratch (allocation-free rule: __device__ globals; zero-initialized at load)
__device__ __half2 g_xh[(size_t)N_NODES * 64];     // x in half (128 halves/row)
__device__ __half2 g_aggh[(size_t)N_NODES * 64];   // layer-1 mean (half)
__device__ __half2 g_hh[(size_t)N_NODES * 64];     // layer-1 activations (half)
__device__ __half2 g_zh[(size_t)N_NODES * 32];     // h @ W2l^T (half)
__device__ float   g_r[(size_t)N_NODES * CLS];     // h @ W2r^T (self term, fp32)
__device__ __half  g_w1h[128 * 256];               // [n][k] : k<128 W1l, k>=128 W1r
__device__ __half  g_w2h[128 * 128];               // [n][k] : n<64 W2l, n>=64 W2r
__device__ int     g_deg[N_NODES];                 // degree; re-zeroed by agg2_final
__device__ int     g_col[(size_t)N_NODES * CAP];   // bucketed source indices

// ---------------------------------------------------------------------------
// k0: convert x -> half, convert weights -> half, bucket edges by destination.
// ---------------------------------------------------------------------------
__global__ void convert_bucket_kernel(const float* __restrict__ x,
                                      const int* __restrict__ srcs,
                                      const int* __restrict__ dsts,
                                      const float* __restrict__ W1l,
                                      const float* __restrict__ W1r,
                                      const float* __restrict__ W2l,
                                      const float* __restrict__ W2r,
                                      int n_edges) {
    int idx = blockIdx.x * blockDim.x + threadIdx.x;
    const int n_conv = N_NODES * 16;
    if (idx < n_conv) {
        const float4* src = (const float4*)x + idx * 2;
        float4 a = __ldg(src), b = __ldg(src + 1);
        __half2 h0 = __floats2half2_rn(a.x, a.y);
        __half2 h1 = __floats2half2_rn(a.z, a.w);
        __half2 h2 = __floats2half2_rn(b.x, b.y);
        __half2 h3 = __floats2half2_rn(b.z, b.w);
        *((uint4*)g_xh + idx) = make_uint4(*(unsigned*)&h0, *(unsigned*)&h1,
                                           *(unsigned*)&h2, *(unsigned*)&h3);
    }
    // W1 interleave: g_w1h row n (256 halves) = [W1l[n][0..128) | W1r[n][0..128)]
    if (idx < 4096) {                       // 128 rows * 32 chunks of 8
        int n = idx >> 5, cr = idx & 31;
        const float* src = (cr < 16) ? (W1l + n * 128 + cr * 8)
                                     : (W1r + n * 128 + (cr - 16) * 8);
        float4 a = __ldg((const float4*)src), b = __ldg((const float4*)src + 1);
        __half2 h0 = __floats2half2_rn(a.x, a.y);
        __half2 h1 = __floats2half2_rn(a.z, a.w);
        __half2 h2 = __floats2half2_rn(b.x, b.y);
        __half2 h3 = __floats2half2_rn(b.z, b.w);
        *((uint4*)(g_w1h + n * 256) + cr) = make_uint4(*(unsigned*)&h0, *(unsigned*)&h1,
                                                       *(unsigned*)&h2, *(unsigned*)&h3);
    }
    // W2 interleave: g_w2h row n = (n<64 ? W2l[n] : W2r[n-64])
    if (idx < 2048) {                       // 128 rows * 16 chunks of 8
        int n = idx >> 4, cr = idx & 15;
        const float* src = (n < 64) ? (W2l + n * 128 + cr * 8)
                                    : (W2r + (n - 64) * 128 + cr * 8);
        float4 a = __ldg((const float4*)src), b = __ldg((const float4*)src + 1);
        __half2 h0 = __floats2half2_rn(a.x, a.y);
        __half2 h1 = __floats2half2_rn(a.z, a.w);
        __half2 h2 = __floats2half2_rn(b.x, b.y);
        __half2 h3 = __floats2half2_rn(b.z, b.w);
        *((uint4*)(g_w2h + n * 128) + cr) = make_uint4(*(unsigned*)&h0, *(unsigned*)&h1,
                                                       *(unsigned*)&h2, *(unsigned*)&h3);
    }
    if (idx < n_edges) {
        int s = __ldg(srcs + idx);
        int d = __ldg(dsts + idx);
        if ((unsigned)s < N_NODES && (unsigned)d < N_NODES) {
            int pos = atomicAdd(g_deg + d, 1);
            if (pos < CAP) g_col[(size_t)d * CAP + pos] = s;
        }
    }
}

// ---------------------------------------------------------------------------
// half helpers
// ---------------------------------------------------------------------------
__device__ __forceinline__ void acc_half8(float* acc, uint4 u) {
    float2 f0 = __half22float2(*(__half2*)&u.x);
    float2 f1 = __half22float2(*(__half2*)&u.y);
    float2 f2 = __half22float2(*(__half2*)&u.z);
    float2 f3 = __half22float2(*(__half2*)&u.w);
    acc[0] += f0.x; acc[1] += f0.y; acc[2] += f1.x; acc[3] += f1.y;
    acc[4] += f2.x; acc[5] += f2.y; acc[6] += f3.x; acc[7] += f3.y;
}

// ---------------------------------------------------------------------------
// Aggregate layer 1: 16 lanes per node (2 nodes/warp), uint4 gathers.
// mean of half x rows -> g_aggh (half).
// ---------------------------------------------------------------------------
__global__ void aggregate1_kernel() {
    int gt   = blockIdx.x * blockDim.x + threadIdx.x;
    int node = gt >> 4;
    int lane = gt & 15;
    if (node >= N_NODES) return;
    int deg = __ldg(g_deg + node);
    int len = min(deg, CAP);
    const int* cols = g_col + (size_t)node * CAP;

    float acc[8];
#pragma unroll
    for (int j = 0; j < 8; j++) acc[j] = 0.f;

    int i = 0;
    for (; i + 4 <= len; i += 4) {
        int4 s4 = *(const int4*)(cols + i);
        uint4 u0 = __ldg((const uint4*)(g_xh + (size_t)s4.x * 64) + lane);
        uint4 u1 = __ldg((const uint4*)(g_xh + (size_t)s4.y * 64) + lane);
        uint4 u2 = __ldg((const uint4*)(g_xh + (size_t)s4.z * 64) + lane);
        uint4 u3 = __ldg((const uint4*)(g_xh + (size_t)s4.w * 64) + lane);
        acc_half8(acc, u0); acc_half8(acc, u1);
        acc_half8(acc, u2); acc_half8(acc, u3);
    }
    for (; i < len; i++) {
        int s = __ldg(cols + i);
        uint4 u = __ldg((const uint4*)(g_xh + (size_t)s * 64) + lane);
        acc_half8(acc, u);
    }
    float inv = (deg > 0) ? 1.0f / (float)deg : 1.0f;
    __half2 h0 = __floats2half2_rn(acc[0] * inv, acc[1] * inv);
    __half2 h1 = __floats2half2_rn(acc[2] * inv, acc[3] * inv);
    __half2 h2 = __floats2half2_rn(acc[4] * inv, acc[5] * inv);
    __half2 h3 = __floats2half2_rn(acc[6] * inv, acc[7] * inv);
    *((uint4*)(g_aggh + (size_t)node * 64) + lane) =
        make_uint4(*(unsigned*)&h0, *(unsigned*)&h1, *(unsigned*)&h2, *(unsigned*)&h3);
}

// ---------------------------------------------------------------------------
// FP16 tensor-core GEMM infrastructure (m16n8k16, fp32 accum).
// ---------------------------------------------------------------------------
#define SMST1   36                        // gemm1: uints per row (64 halves + pad)
#define TILE1_U (128 * SMST1)             // 4608
#define STAGE1_U (2 * TILE1_U)
#define GSMEM1_BYTES (3 * STAGE1_U * 4)   // 110592 (3 stages)

#define SMST2   68                        // gemm2: uints per row (128 halves + pad)
#define TILE2_U (128 * SMST2)             // 8704
#define GSMEM2_BYTES (2 * TILE2_U * 4)    // 69632 (A + B, single phase)

#define MMA_F16(c, a, b)                                                      \
    asm volatile("mma.sync.aligned.m16n8k16.row.col.f32.f16.f16.f32 "         \
                 "{%0,%1,%2,%3}, {%4,%5,%6,%7}, {%8,%9}, {%0,%1,%2,%3};"      \
                 : "+f"((c)[0]), "+f"((c)[1]), "+f"((c)[2]), "+f"((c)[3])     \
                 : "r"((a)[0]), "r"((a)[1]), "r"((a)[2]), "r"((a)[3]),        \
                   "r"((b)[0]), "r"((b)[1]))

__device__ __forceinline__ void cp_async16(unsigned saddr, const void* gptr) {
    asm volatile("cp.async.cg.shared.global [%0], [%1], 16;"
                 :: "r"(saddr), "l"(gptr));
}
__device__ __forceinline__ void cp_commit() {
    asm volatile("cp.async.commit_group;");
}
template <int N>
__device__ __forceinline__ void cp_wait() {
    asm volatile("cp.async.wait_group %0;" :: "n"(N));
}

// NSTEPS k16-steps of MMA over smem tiles with row stride STRIDE uints.
template <int STRIDE, int NSTEPS>
__device__ __forceinline__ void mma_tile(const unsigned* As, const unsigned* Bs,
                                         int wm, int wn, int g, int tig,
                                         float acc[2][8][4]) {
#pragma unroll
    for (int ks = 0; ks < NSTEPS; ks++) {
        int k0 = ks * 8;                 // 16 halves = 8 uints
        unsigned afr[2][4], bfr[8][2];
#pragma unroll
        for (int mt = 0; mt < 2; mt++) {
            int r = wm * 32 + mt * 16 + g;
            afr[mt][0] = As[r * STRIDE + k0 + tig];
            afr[mt][1] = As[(r + 8) * STRIDE + k0 + tig];
            afr[mt][2] = As[r * STRIDE + k0 + tig + 4];
            afr[mt][3] = As[(r + 8) * STRIDE + k0 + tig + 4];
        }
#pragma unroll
        for (int nt = 0; nt < 8; nt++) {
            int c = wn * 64 + nt * 8 + g;
            bfr[nt][0] = Bs[c * STRIDE + k0 + tig];
            bfr[nt][1] = Bs[c * STRIDE + k0 + tig + 4];
        }
#pragma unroll
        for (int mt = 0; mt < 2; mt++)
#pragma unroll
            for (int nt = 0; nt < 8; nt++)
                MMA_F16(acc[mt][nt], afr[mt], bfr[nt]);
    }
}

// GEMM1: h = relu([mean | x] @ [W1l; W1r]^T + b1l), K = 256 halves,
// 4 k-tiles of 64 halves, 3-stage cp.async pipeline, one sync per iter.
__global__ __launch_bounds__(256, 2)
void gemm1_tc(const float* __restrict__ b1l) {
    extern __shared__ unsigned smem[];

    int t    = threadIdx.x;
    int lane = t & 31, w = t >> 5;
    int g    = lane >> 2, tig = lane & 3;
    int wm   = w & 3, wn = w >> 2;
    int m0   = blockIdx.x * 128;

    float acc[2][8][4];
#pragma unroll
    for (int mt = 0; mt < 2; mt++)
#pragma unroll
        for (int nt = 0; nt < 8; nt++)
#pragma unroll
            for (int i = 0; i < 4; i++) acc[mt][nt][i] = 0.f;

    unsigned sbase = (unsigned)__cvta_generic_to_shared(smem);

    // tile = 0..3, each covers 64 halves of the 256-half concat K
    auto copy_tile = [&](int tile, int buf) {
        const __half2* Asrc = (tile < 2) ? g_aggh : g_xh;
        int ah2 = (tile & 1) * 32;               // half2 offset within row
        unsigned abase = sbase + buf * STAGE1_U * 4;
        unsigned bbase = abase + TILE1_U * 4;
#pragma unroll
        for (int c = 0; c < 4; c++) {
            int cid = t * 4 + c;                 // 0..1023
            int row = cid >> 3, ch = cid & 7;    // 8 x 16B chunks per row
            int arow = m0 + row;
            int crow = (arow < N_NODES) ? arow : (N_NODES - 1);
            cp_async16(abase + (row * SMST1 + ch * 4) * 4,
                       Asrc + (size_t)crow * 64 + ah2 + ch * 4);
            cp_async16(bbase + (row * SMST1 + ch * 4) * 4,
                       g_w1h + (size_t)row * 256 + tile * 64 + ch * 8);
        }
    };

    copy_tile(0, 0); cp_commit();
    copy_tile(1, 1); cp_commit();

#pragma unroll 1
    for (int tile = 0; tile < 4; tile++) {
        if (tile < 3) cp_wait<1>(); else cp_wait<0>();
        __syncthreads();
        const unsigned* As = smem + (tile % 3) * STAGE1_U;
        const unsigned* Bs = As + TILE1_U;
        mma_tile<SMST1, 4>(As, Bs, wm, wn, g, tig, acc);
        if (tile + 2 < 4) {
            copy_tile(tile + 2, (tile + 2) % 3);
            cp_commit();
        }
    }

    // Epilogue: bias + relu -> g_hh (half)
#pragma unroll
    for (int nt = 0; nt < 8; nt++) {
        int col = wn * 64 + nt * 8 + 2 * tig;
        float2 bias = __ldg((const float2*)(b1l + col));
#pragma unroll
        for (int mt = 0; mt < 2; mt++) {
            int r = m0 + wm * 32 + mt * 16 + g;
            if (r < N_NODES) {
                __half2 o = __floats2half2_rn(
                    fmaxf(acc[mt][nt][0] + bias.x, 0.f),
                    fmaxf(acc[mt][nt][1] + bias.y, 0.f));
                g_hh[(size_t)r * 64 + (col >> 1)] = o;
            }
            if (r + 8 < N_NODES) {
                __half2 o = __floats2half2_rn(
                    fmaxf(acc[mt][nt][2] + bias.x, 0.f),
                    fmaxf(acc[mt][nt][3] + bias.y, 0.f));
                g_hh[(size_t)(r + 8) * 64 + (col >> 1)] = o;
            }
        }
    }
}

// GEMM2: y = h @ [W2l; W2r]^T (K = 128 halves). SINGLE PHASE: whole A+B tile
// loaded in one cp.async batch, one sync, then 8 uninterrupted k-steps.
// Cols <64 -> g_zh (half), >=64 -> g_r (fp32).
__global__ __launch_bounds__(256, 2)
void gemm2_tc() {
    extern __shared__ unsigned smem[];

    int t    = threadIdx.x;
    int lane = t & 31, w = t >> 5;
    int g    = lane >> 2, tig = lane & 3;
    int wm   = w & 3, wn = w >> 2;
    int m0   = blockIdx.x * 128;

    float acc[2][8][4];
#pragma unroll
    for (int mt = 0; mt < 2; mt++)
#pragma unroll
        for (int nt = 0; nt < 8; nt++)
#pragma unroll
            for (int i = 0; i < 4; i++) acc[mt][nt][i] = 0.f;

    unsigned sbase = (unsigned)__cvta_generic_to_shared(smem);
    unsigned bbase = sbase + TILE2_U * 4;

    // A: 128 rows x 256 B = 2048 chunks; B: same. 8+8 chunks per thread.
#pragma unroll
    for (int c = 0; c < 8; c++) {
        int cid = t * 8 + c;                 // 0..2047
        int row = cid >> 4, ch = cid & 15;   // 16 x 16B chunks per row
        int arow = m0 + row;
        int crow = (arow < N_NODES) ? arow : (N_NODES - 1);
        cp_async16(sbase + (row * SMST2 + ch * 4) * 4,
                   g_hh + (size_t)crow * 64 + ch * 4);
        cp_async16(bbase + (row * SMST2 + ch * 4) * 4,
                   g_w2h + (size_t)row * 128 + ch * 8);
    }
    cp_commit();
    cp_wait<0>();
    __syncthreads();

    mma_tile<SMST2, 8>(smem, smem + TILE2_U, wm, wn, g, tig, acc);

#pragma unroll
    for (int nt = 0; nt < 8; nt++) {
        int col = wn * 64 + nt * 8 + 2 * tig;
#pragma unroll
        for (int mt = 0; mt < 2; mt++) {
            int r = m0 + wm * 32 + mt * 16 + g;
            if (col < 64) {
                if (r < N_NODES)
                    g_zh[(size_t)r * 32 + (col >> 1)] =
                        __floats2half2_rn(acc[mt][nt][0], acc[mt][nt][1]);
                if (r + 8 < N_NODES)
                    g_zh[(size_t)(r + 8) * 32 + (col >> 1)] =
                        __floats2half2_rn(acc[mt][nt][2], acc[mt][nt][3]);
            } else {
                int c2 = col - 64;
                if (r < N_NODES)
                    *(float2*)(g_r + (size_t)r * CLS + c2) =
                        make_float2(acc[mt][nt][0], acc[mt][nt][1]);
                if (r + 8 < N_NODES)
                    *(float2*)(g_r + (size_t)(r + 8) * CLS + c2) =
                        make_float2(acc[mt][nt][2], acc[mt][nt][3]);
            }
        }
    }
}

// ---------------------------------------------------------------------------
// Fused aggregate2 + bias + self-term + log_softmax + store. 8 lanes/node,
// uint4 gathers. Also resets g_deg (invariant restore for graph replay).
// ---------------------------------------------------------------------------
__global__ void agg2_final_kernel(const float* __restrict__ b2l,
                                  float* __restrict__ out) {
    int gt   = blockIdx.x * blockDim.x + threadIdx.x;
    int node = gt >> 3;
    int lane = gt & 7;
    if (node >= N_NODES) return;
    int deg = __ldg(g_deg + node);
    int len = min(deg, CAP);
    const int* cols = g_col + (size_t)node * CAP;

    float acc[8];
#pragma unroll
    for (int j = 0; j < 8; j++) acc[j] = 0.f;

    int i = 0;
    for (; i + 4 <= len; i += 4) {
        int4 s4 = *(const int4*)(cols + i);
        uint4 u0 = __ldg((const uint4*)(g_zh + (size_t)s4.x * 32) + lane);
        uint4 u1 = __ldg((const uint4*)(g_zh + (size_t)s4.y * 32) + lane);
        uint4 u2 = __ldg((const uint4*)(g_zh + (size_t)s4.z * 32) + lane);
        uint4 u3 = __ldg((const uint4*)(g_zh + (size_t)s4.w * 32) + lane);
        acc_half8(acc, u0); acc_half8(acc, u1);
        acc_half8(acc, u2); acc_half8(acc, u3);
    }
    for (; i < len; i++) {
        int s = __ldg(cols + i);
        uint4 u = __ldg((const uint4*)(g_zh + (size_t)s * 32) + lane);
        acc_half8(acc, u);
    }
    float inv = (deg > 0) ? 1.0f / (float)deg : 1.0f;

    const float* rrow = g_r + (size_t)node * CLS + lane * 8;
    float4 r0 = *(const float4*)rrow;
    float4 r1 = *(const float4*)(rrow + 4);
    float4 b0 = __ldg((const float4*)(b2l + lane * 8));
    float4 b1 = __ldg((const float4*)(b2l + lane * 8 + 4));

    float v[8];
    v[0] = acc[0] * inv + b0.x + r0.x;
    v[1] = acc[1] * inv + b0.y + r0.y;
    v[2] = acc[2] * inv + b0.z + r0.z;
    v[3] = acc[3] * inv + b0.w + r0.w;
    v[4] = acc[4] * inv + b1.x + r1.x;
    v[5] = acc[5] * inv + b1.y + r1.y;
    v[6] = acc[6] * inv + b1.z + r1.z;
    v[7] = acc[7] * inv + b1.w + r1.w;

    float rmax = v[0];
#pragma unroll
    for (int j = 1; j < 8; j++) rmax = fmaxf(rmax, v[j]);
#pragma unroll
    for (int off = 4; off > 0; off >>= 1)
        rmax = fmaxf(rmax, __shfl_xor_sync(0xffffffffu, rmax, off));
    float s = 0.f;
#pragma unroll
    for (int j = 0; j < 8; j++) s += expf(v[j] - rmax);
#pragma unroll
    for (int off = 4; off > 0; off >>= 1)
        s += __shfl_xor_sync(0xffffffffu, s, off);
    float lse = logf(s) + rmax;

    float* orow = out + (size_t)node * CLS + lane * 8;
    *(float4*)orow       = make_float4(v[0] - lse, v[1] - lse, v[2] - lse, v[3] - lse);
    *(float4*)(orow + 4) = make_float4(v[4] - lse, v[5] - lse, v[6] - lse, v[7] - lse);

    if (lane == 0) g_deg[node] = 0;   // restore launch-start invariant
}

// ---------------------------------------------------------------------------
// Launch (5 kernels)
// ---------------------------------------------------------------------------
extern "C" void kernel_launch(void* const* d_in, const int* in_sizes, int n_in,
                              void* d_out, int out_size) {
    const float* x    = (const float*)d_in[0];
    const int*   ei   = (const int*)d_in[1];
    const float* W1l  = (const float*)d_in[2];
    const float* b1l  = (const float*)d_in[3];
    const float* W1r  = (const float*)d_in[4];
    const float* W2l  = (const float*)d_in[5];
    const float* b2l  = (const float*)d_in[6];
    const float* W2r  = (const float*)d_in[7];
    float*       out  = (float*)d_out;

    const int n_edges = in_sizes[1] / 2;
    const int* srcs = ei;
    const int* dsts = ei + n_edges;

    int cb_threads = N_NODES * 16;
    if (n_edges > cb_threads) cb_threads = n_edges;
    const int cb_blocks   = (cb_threads + 255) / 256;
    const int agg1_blocks = (N_NODES * 16 + 255) / 256;
    const int gemm_blocks = (N_NODES + 127) / 128;
    const int fin_blocks  = (N_NODES * 8 + 255) / 256;

    cudaFuncSetAttribute(gemm1_tc, cudaFuncAttributeMaxDynamicSharedMemorySize, GSMEM1_BYTES);
    cudaFuncSetAttribute(gemm2_tc, cudaFuncAttributeMaxDynamicSharedMemorySize, GSMEM2_BYTES);

    convert_bucket_kernel<<<cb_blocks, 256>>>(x, srcs, dsts, W1l, W1r, W2l, W2r, n_edges);
    aggregate1_kernel<<<agg1_blocks, 256>>>();
    gemm1_tc<<<gemm_blocks, 256, GSMEM1_BYTES>>>(b1l);
    gemm2_tc<<<gemm_blocks, 256, GSMEM2_BYTES>>>();
    agg2_final_kernel<<<fin_blocks, 256>>>(b2l, out);
}